// round 2
// baseline (speedup 1.0000x reference)
#include <cuda_runtime.h>
#include <cstdint>

// ---------------- problem-scale constants ----------------
#define CHUNK   1024
#define MAXN    262144          // >= N (200000)
#define MAXCH   256             // MAXN / CHUNK
#define NBPAD   8448            // padded bin stride (>= MAXC+1, >= 4096)
#define MAXC    8192            // max condensation points
#define IDXBITS 21
#define IDXMASK ((1u<<IDXBITS)-1u)
#define RAD2    2.25f
#define MINBETA 0.8f

// ---------------- device scratch (static: no allocation) ----------------
static __device__ uint64_t g_keyA[MAXN];
static __device__ uint64_t g_keyB[MAXN];
static __device__ int      g_hist[MAXCH * NBPAD];
static __device__ int      g_total[NBPAD];
static __device__ int      g_start[NBPAD];
static __device__ int      g_dense[NBPAD];
static __device__ int      g_ccnt[MAXCH];
static __device__ int      g_coff[MAXCH];
static __device__ float4   g_cp[MAXC];        // x,y,z, w=bits(seg<<21|origidx)
static __device__ int      g_cpid2bin[MAXC];  // greedy rank -> bin (1-based)
static __device__ int      g_g[MAXN];         // greedy rank of asso cpoint, or -1
static __device__ int      g_pos[MAXN];       // sorted position of point i
static __device__ int      g_M;               // candidate count
static __device__ int      g_nC;              // cpoint count

// ---------------- helpers ----------------
__device__ __forceinline__ int blkscan_excl(int v, int tid, int* ws) {
    // 1024-thread block exclusive scan
    __syncthreads();
    int lane = tid & 31, w = tid >> 5;
    int inc = v;
    #pragma unroll
    for (int o = 1; o < 32; o <<= 1) {
        int u = __shfl_up_sync(0xffffffffu, inc, o);
        if (lane >= o) inc += u;
    }
    if (lane == 31) ws[w] = inc;
    __syncthreads();
    if (tid < 32) {
        int s = ws[tid];
        #pragma unroll
        for (int o = 1; o < 32; o <<= 1) {
            int u = __shfl_up_sync(0xffffffffu, s, o);
            if (lane >= o) s += u;
        }
        ws[tid] = s;
    }
    __syncthreads();
    return (w ? ws[w - 1] : 0) + inc - v;
}

__device__ __forceinline__ int seg_of(int i, const int* rs, int ns) {
    int s = 0;
    for (int j = 1; j < ns - 1; j++) s += (i >= rs[j]);
    return s;
}

__device__ __forceinline__ float dist2(float ax, float ay, float az,
                                       float bx, float by, float bz) {
    float dx = ax - bx, dy = ay - by, dz = az - bz;
    return fmaf(dz, dz, fmaf(dy, dy, dx * dx));   // matches XLA fma reduce chain
}

// ---------------- kernels ----------------
__global__ void k_init(float* psrs, int n) {
    int t = blockIdx.x * blockDim.x + threadIdx.x;
    if (t <= n) psrs[t] = (float)n;
}

__global__ __launch_bounds__(1024) void k_candcount(const float* __restrict__ betas, int n) {
    int t = blockIdx.x * CHUNK + threadIdx.x;
    int pred = (t < n) && (betas[t] >= MINBETA);
    int cnt = __syncthreads_count(pred);
    if (threadIdx.x == 0) g_ccnt[blockIdx.x] = cnt;
}

__global__ void k_candscan(int nch) {
    if (threadIdx.x == 0) {
        int s = 0;
        for (int c = 0; c < nch; c++) { g_coff[c] = s; s += g_ccnt[c]; }
        g_M = s;
    }
}

__global__ __launch_bounds__(1024) void k_candscatter(const float* __restrict__ betas, int n) {
    __shared__ int ws[32];
    int tid = threadIdx.x;
    int t = blockIdx.x * CHUNK + tid;
    int pred = (t < n) && (betas[t] >= MINBETA);
    int lr = blkscan_excl(pred, tid, ws);
    if (pred) {
        unsigned bits = __float_as_uint(betas[t]);
        uint64_t m = (~bits) & 0x7FFFFFu;               // exponent constant on [0.8,1)
        g_keyA[g_coff[blockIdx.x] + lr] = (m << IDXBITS) | (unsigned)t;
    }
}

// radix histogram (power-of-2 nb <= 4096), srcSel: 0=A,1=B
__global__ __launch_bounds__(1024) void k_histR(int srcSel, int shift, int nb) {
    __shared__ int h[4096];
    int tid = threadIdx.x;
    for (int b = tid; b < nb; b += 1024) h[b] = 0;
    __syncthreads();
    const uint64_t* keys = srcSel ? g_keyB : g_keyA;
    int M = g_M;
    int t = blockIdx.x * CHUNK + tid;
    if (t < M) atomicAdd(&h[(int)((keys[t] >> shift) & (nb - 1))], 1);
    __syncthreads();
    for (int b = tid; b < nb; b += 1024) g_hist[blockIdx.x * NBPAD + b] = h[b];
}

__global__ void k_colsum(int nch, int nbFixed, int useC) {
    int nb = useC ? (g_nC + 1) : nbFixed;
    int b = blockIdx.x * blockDim.x + threadIdx.x;
    if (b < nb) {
        int s = 0;
        for (int c = 0; c < nch; c++) s += g_hist[c * NBPAD + b];
        g_total[b] = s;
    }
}

__global__ __launch_bounds__(1024) void k_scan(int nbFixed, int useC, float* psrs, int finalMode) {
    __shared__ int ws[32];
    int nb = useC ? (g_nC + 1) : nbFixed;
    int tid = threadIdx.x;
    const int IT = 9;                  // 9*1024 >= NBPAD
    int base = tid * IT;
    int loc[IT]; int s = 0;
    #pragma unroll
    for (int j = 0; j < IT; j++) {
        loc[j] = (base + j < nb) ? g_total[base + j] : 0;
        s += loc[j];
    }
    int ex = blkscan_excl(s, tid, ws);
    int run = ex;
    #pragma unroll
    for (int j = 0; j < IT; j++) {
        if (base + j < nb) g_start[base + j] = run;
        run += loc[j];
    }
    if (finalMode) {
        int occ[IT]; int so = 0;
        #pragma unroll
        for (int j = 0; j < IT; j++) { occ[j] = (base + j < nb && loc[j] > 0) ? 1 : 0; so += occ[j]; }
        int ex2 = blkscan_excl(so, tid, ws);
        int run2 = ex2, runS = ex;
        #pragma unroll
        for (int j = 0; j < IT; j++) {
            if (base + j < nb) {
                g_dense[base + j] = run2;
                if (occ[j]) psrs[run2] = (float)runS;
                run2 += occ[j];
            }
            runS += loc[j];
        }
        if (tid == 0) psrs[0] = 0.0f;
    }
}

__global__ void k_offsets(int nch, int nbFixed, int useC) {
    int nb = useC ? (g_nC + 1) : nbFixed;
    int b = blockIdx.x * blockDim.x + threadIdx.x;
    if (b >= nb) return;
    int run = g_start[b];
    for (int c = 0; c < nch; c++) {
        int idx = c * NBPAD + b;
        int t = g_hist[idx];
        g_hist[idx] = run;
        run += t;
    }
}

// stable radix scatter; srcSel 0: A->B, 1: B->A
__global__ __launch_bounds__(1024) void k_scatterR(int srcSel, int shift, int nb) {
    __shared__ int dig[CHUNK];
    __shared__ uint64_t ky[CHUNK];
    const uint64_t* in = srcSel ? g_keyB : g_keyA;
    uint64_t* out = srcSel ? g_keyA : g_keyB;
    int tid = threadIdx.x;
    int M = g_M;
    int t = blockIdx.x * CHUNK + tid;
    int d = -7;
    if (t < M) {
        uint64_t k = in[t];
        ky[tid] = k;
        d = (int)((k >> shift) & (nb - 1));
    }
    dig[tid] = d;
    __syncthreads();
    int lr = 0;
    for (int q = 0; q < tid; q++) lr += (dig[q] == d);   // broadcast smem reads
    if (t < M) out[g_hist[blockIdx.x * NBPAD + d] + lr] = ky[tid];
}

// ---------------- greedy NMS over sorted candidates (single block) ----------------
#define GREEDY_SMEM (131072 + 3*4096 + 4096 + 4096 + 4096 + 128)
__global__ __launch_bounds__(1024) void k_greedy(const float* __restrict__ cc,
                                                 const int* __restrict__ rs, int ns) {
    extern __shared__ char sm[];
    float4* scp  = (float4*)sm;                         // 8192*16
    float*  chx  = (float*)(sm + 131072);
    float*  chy  = (float*)(sm + 131072 + 4096);
    float*  chz  = (float*)(sm + 131072 + 8192);
    int*    chsi = (int*)  (sm + 131072 + 12288);
    int*    surv = (int*)  (sm + 131072 + 16384);
    int*    salv = (int*)  (sm + 131072 + 20480);
    int*    wsum = (int*)  (sm + 131072 + 24576);
    __shared__ int snC;
    int tid = threadIdx.x;
    if (tid == 0) snC = 0;
    __syncthreads();
    int M = g_M;
    int nchunks = (M + CHUNK - 1) / CHUNK;
    for (int ch = 0; ch < nchunks; ch++) {
        int t = ch * CHUNK + tid;
        bool valid = t < M;
        float x = 0.f, y = 0.f, z = 0.f; int si = 0;
        if (valid) {
            uint64_t k = g_keyA[t];
            int i = (int)(k & IDXMASK);
            x = cc[3*i]; y = cc[3*i+1]; z = cc[3*i+2];
            si = (seg_of(i, rs, ns) << IDXBITS) | i;
        }
        chx[tid] = x; chy[tid] = y; chz[tid] = z; chsi[tid] = si;
        int myseg = si >> IDXBITS;
        bool alive = valid;
        int nC = snC;
        for (int c = 0; c < nC && alive; c++) {
            float4 p = scp[c];
            if ((__float_as_int(p.w) >> IDXBITS) == myseg)
                if (dist2(x, y, z, p.x, p.y, p.z) <= RAD2) alive = false;
        }
        // order-preserving compaction of survivors
        unsigned b = __ballot_sync(0xffffffffu, alive);
        int lane = tid & 31, w = tid >> 5;
        if (lane == 0) wsum[w] = __popc(b);
        __syncthreads();
        if (tid < 32) {
            int v = wsum[tid];
            #pragma unroll
            for (int o = 1; o < 32; o <<= 1) {
                int u = __shfl_up_sync(0xffffffffu, v, o);
                if (lane >= o) v += u;
            }
            wsum[tid] = v;
        }
        __syncthreads();
        int S = wsum[31];
        if (alive) {
            int slot = (w ? wsum[w - 1] : 0) + __popc(b & ((1u << lane) - 1u));
            surv[slot] = tid; salv[slot] = 1;
        }
        __syncthreads();
        // sequential resolve among survivors (greedy order preserved)
        for (int s = 0; s < S; s++) {
            if (salv[s]) {
                int j = surv[s];
                float sx = chx[j], sy = chy[j], sz = chz[j];
                int ssi = chsi[j];
                if (tid == 0 && snC < MAXC) {
                    scp[snC] = make_float4(sx, sy, sz, __int_as_float(ssi));
                    snC++;
                }
                if (tid > s && tid < S && salv[tid]) {
                    int jj = surv[tid];
                    if ((chsi[jj] >> IDXBITS) == (ssi >> IDXBITS))
                        if (dist2(chx[jj], chy[jj], chz[jj], sx, sy, sz) <= RAD2)
                            salv[tid] = 0;
                }
            }
            __syncthreads();
        }
        __syncthreads();
    }
    int nC = snC;
    for (int c = tid; c < nC; c += 1024) g_cp[c] = scp[c];
    if (tid == 0) g_nC = nC;
}

// sort cpoint original indices ascending; greedy-rank -> (1-based) bin
__global__ __launch_bounds__(1024) void k_cpsort() {
    extern __shared__ uint64_t sk[];    // 8192 * 8B
    int nC = g_nC;
    int tid = threadIdx.x;
    for (int e = tid; e < MAXC; e += 1024)
        sk[e] = (e < nC)
            ? ((((uint64_t)(__float_as_int(g_cp[e].w) & IDXMASK)) << 13) | (unsigned)e)
            : ~0ull;
    __syncthreads();
    for (int k = 2; k <= MAXC; k <<= 1)
        for (int j = k >> 1; j > 0; j >>= 1) {
            for (int e = tid; e < MAXC; e += 1024) {
                int x = e ^ j;
                if (x > e) {
                    uint64_t a = sk[e], b = sk[x];
                    bool up = ((e & k) == 0);
                    if ((a > b) == up) { sk[e] = b; sk[x] = a; }
                }
            }
            __syncthreads();
        }
    for (int r = tid; r < nC; r += 1024)
        g_cpid2bin[(int)(sk[r] & 0x1FFFu)] = r + 1;
}

// assignment: first cpoint in greedy order within radius & same segment
__global__ __launch_bounds__(512) void k_phase2(const float* __restrict__ cc,
                                                const int* __restrict__ rs, int ns,
                                                int n, float* __restrict__ asso_out) {
    extern __shared__ float4 scache[];  // 4096
    int nC = g_nC;
    int lim = nC < 4096 ? nC : 4096;
    for (int c = threadIdx.x; c < lim; c += blockDim.x) scache[c] = g_cp[c];
    __syncthreads();
    int i = blockIdx.x * blockDim.x + threadIdx.x;
    if (i >= n) return;
    float x = cc[3*i], y = cc[3*i+1], z = cc[3*i+2];
    int seg = seg_of(i, rs, ns);
    int g = -1, assov = -1;
    for (int c = 0; c < nC; c++) {
        float4 p = (c < lim) ? scache[c] : g_cp[c];
        int psi = __float_as_int(p.w);
        if ((psi >> IDXBITS) == seg) {
            if (dist2(x, y, z, p.x, p.y, p.z) <= RAD2) {
                g = c; assov = psi & (int)IDXMASK; break;
            }
        }
    }
    g_g[i] = g;
    asso_out[i] = (float)((g < 0) ? -1 : assov);
}

__global__ __launch_bounds__(1024) void k_hist2(int n) {
    __shared__ int h[NBPAD];
    int nb = g_nC + 1;
    int tid = threadIdx.x;
    for (int b = tid; b < nb; b += 1024) h[b] = 0;
    __syncthreads();
    int t = blockIdx.x * CHUNK + tid;
    if (t < n) {
        int g = g_g[t];
        int b = (g < 0) ? 0 : g_cpid2bin[g];
        atomicAdd(&h[b], 1);
    }
    __syncthreads();
    for (int b = tid; b < nb; b += 1024) g_hist[blockIdx.x * NBPAD + b] = h[b];
}

__global__ __launch_bounds__(1024) void k_scatter2(int n, float* __restrict__ sids,
                                                   float* __restrict__ belongs) {
    __shared__ int dig[CHUNK];
    int tid = threadIdx.x;
    int t = blockIdx.x * CHUNK + tid;
    int d = -7;
    if (t < n) {
        int g = g_g[t];
        d = (g < 0) ? 0 : g_cpid2bin[g];
    }
    dig[tid] = d;
    __syncthreads();
    int lr = 0;
    for (int q = 0; q < tid; q++) lr += (dig[q] == d);
    if (t < n) {
        int pos = g_hist[blockIdx.x * NBPAD + d] + lr;
        g_pos[t] = pos;
        sids[pos] = (float)t;
        belongs[pos] = (float)g_dense[d];
    }
}

__global__ __launch_bounds__(512) void k_copy(const float* __restrict__ data,
                                              float* __restrict__ sdata, int n, int F) {
    int warp = (blockIdx.x * blockDim.x + threadIdx.x) >> 5;
    int lane = threadIdx.x & 31;
    if (warp >= n) return;
    int pos = g_pos[warp];
    const float4* src = (const float4*)(data + (size_t)warp * F);
    float4* dst = (float4*)(sdata + (size_t)pos * F);
    int nf4 = F >> 2;
    for (int k = lane; k < nf4; k += 32) dst[k] = src[k];
}

// ---------------- host launcher ----------------
extern "C" void kernel_launch(void* const* d_in, const int* in_sizes, int n_in,
                              void* d_out, int out_size) {
    const float* data  = (const float*)d_in[0];
    const float* cc    = (const float*)d_in[1];
    const float* betas = (const float*)d_in[2];
    const int*   rs    = (const int*)d_in[3];
    int N = in_sizes[2];                 // betas is (N,1)
    int F = in_sizes[0] / N;             // 128
    int ns = in_sizes[3];                // 3

    float* out    = (float*)d_out;
    float* sdata  = out;
    float* psrs   = out + (size_t)N * F;
    float* sids   = psrs + (N + 1);
    float* asso   = sids + N;
    float* belongs= asso + N;

    int nch = (N + CHUNK - 1) / CHUNK;

    cudaFuncSetAttribute(k_greedy, cudaFuncAttributeMaxDynamicSharedMemorySize, GREEDY_SMEM);
    cudaFuncSetAttribute(k_cpsort, cudaFuncAttributeMaxDynamicSharedMemorySize, MAXC * 8);
    cudaFuncSetAttribute(k_phase2, cudaFuncAttributeMaxDynamicSharedMemorySize, 4096 * 16);

    k_init<<<(N + 1 + 1023) / 1024, 1024>>>(psrs, N);

    // candidate compaction (index-stable)
    k_candcount<<<nch, 1024>>>(betas, N);
    k_candscan<<<1, 32>>>(nch);
    k_candscatter<<<nch, 1024>>>(betas, N);

    // 2-pass LSD radix on mantissa bits [21..43] of key (stable -> idx tiebreak)
    // pass 1: bits 21..32 (12 bits), A -> B
    k_histR<<<nch, 1024>>>(0, 21, 4096);
    k_colsum<<<(NBPAD + 255) / 256, 256>>>(nch, 4096, 0);
    k_scan<<<1, 1024>>>(4096, 0, psrs, 0);
    k_offsets<<<(NBPAD + 255) / 256, 256>>>(nch, 4096, 0);
    k_scatterR<<<nch, 1024>>>(0, 21, 4096);
    // pass 2: bits 33..43 (11 bits), B -> A
    k_histR<<<nch, 1024>>>(1, 33, 2048);
    k_colsum<<<(NBPAD + 255) / 256, 256>>>(nch, 2048, 0);
    k_scan<<<1, 1024>>>(2048, 0, psrs, 0);
    k_offsets<<<(NBPAD + 255) / 256, 256>>>(nch, 2048, 0);
    k_scatterR<<<nch, 1024>>>(1, 33, 2048);

    // greedy NMS -> cpoint list in greedy order
    k_greedy<<<1, 1024, GREEDY_SMEM>>>(cc, rs, ns);
    // sort cpoint original indices -> bin mapping
    k_cpsort<<<1, 1024, MAXC * 8>>>();
    // per-point assignment + asso output
    k_phase2<<<(N + 511) / 512, 512, 4096 * 16>>>(cc, rs, ns, N, asso);

    // final stable counting sort by bin
    k_hist2<<<nch, 1024>>>(N);
    k_colsum<<<(NBPAD + 255) / 256, 256>>>(nch, 0, 1);
    k_scan<<<1, 1024>>>(0, 1, psrs, 1);   // also writes psrs + dense ranks
    k_offsets<<<(NBPAD + 255) / 256, 256>>>(nch, 0, 1);
    k_scatter2<<<nch, 1024>>>(N, sids, belongs);

    // permute data rows (HBM-bound: ~205 MB)
    k_copy<<<(N + 15) / 16, 512>>>(data, sdata, N, F);
}

// round 3
// speedup vs baseline: 1.4132x; 1.4132x over previous
#include <cuda_runtime.h>
#include <cstdint>

// ---------------- problem-scale constants ----------------
#define CHUNK   1024
#define MAXN    262144          // >= N (200000)
#define MAXCH   256             // MAXN / CHUNK
#define NBPAD   8448            // padded bin stride
#define IDXBITS 21
#define IDXMASK ((1u<<IDXBITS)-1u)
#define RAD2    2.25f
#define MINBETA 0.8f

// spatial grid over cpoints
#define GD      11
#define GHALF   8.25f
#define CINV    0.666f          // cell width ~1.5015 > 1.5 => +-1 cell covers radius
#define GCELLS  (2*GD*GD*GD)    // 2662 (2 segments)
#define MAXCG   2048            // max condensation points

// ---------------- device scratch (static: no allocation) ----------------
static __device__ uint64_t g_keyA[MAXN];
static __device__ uint64_t g_keyB[MAXN];
static __device__ int      g_hist[MAXCH * NBPAD];
static __device__ int      g_total[NBPAD];
static __device__ int      g_start[NBPAD];
static __device__ int      g_dense[NBPAD];
static __device__ int      g_ccnt[MAXCH];
static __device__ int      g_coff[MAXCH];
static __device__ float4   g_cp[MAXCG];        // x,y,z, w=bits(orig idx)
static __device__ int      g_headG[GCELLS];
static __device__ int      g_nxtG[MAXCG];
static __device__ int      g_cpid2bin[MAXCG];  // greedy rank -> bin (1-based)
static __device__ int      g_g[MAXN];          // greedy rank of asso cpoint, or -1
static __device__ int      g_pos[MAXN];        // sorted position of point i
static __device__ int      g_M;                // candidate count
static __device__ int      g_nC;               // cpoint count

// ---------------- helpers ----------------
__device__ __forceinline__ int blkscan_excl(int v, int tid, int* ws) {
    __syncthreads();
    int lane = tid & 31, w = tid >> 5;
    int inc = v;
    #pragma unroll
    for (int o = 1; o < 32; o <<= 1) {
        int u = __shfl_up_sync(0xffffffffu, inc, o);
        if (lane >= o) inc += u;
    }
    if (lane == 31) ws[w] = inc;
    __syncthreads();
    if (tid < 32) {
        int s = ws[tid];
        #pragma unroll
        for (int o = 1; o < 32; o <<= 1) {
            int u = __shfl_up_sync(0xffffffffu, s, o);
            if (lane >= o) s += u;
        }
        ws[tid] = s;
    }
    __syncthreads();
    return (w ? ws[w - 1] : 0) + inc - v;
}

__device__ __forceinline__ float dist2(float ax, float ay, float az,
                                       float bx, float by, float bz) {
    float dx = ax - bx, dy = ay - by, dz = az - bz;
    return fmaf(dz, dz, fmaf(dy, dy, dx * dx));   // matches XLA fma reduce chain
}

__device__ __forceinline__ int cell1(float v) {
    int c = (int)floorf((v + GHALF) * CINV);
    return c < 0 ? 0 : (c > GD - 1 ? GD - 1 : c);
}
__device__ __forceinline__ int cell_of(float x, float y, float z, int seg) {
    return ((seg * GD + cell1(z)) * GD + cell1(y)) * GD + cell1(x);
}

// ---------------- kernels ----------------
__global__ __launch_bounds__(1024) void k_candcount(const float* __restrict__ betas, int n,
                                                    float* __restrict__ psrs) {
    int t = blockIdx.x * CHUNK + threadIdx.x;
    if (t <= n) psrs[t] = (float)n;                 // init psrs padding
    int pred = (t < n) && (betas[t] >= MINBETA);
    int cnt = __syncthreads_count(pred);
    if (threadIdx.x == 0) g_ccnt[blockIdx.x] = cnt;
}

__global__ void k_candscan(int nch) {
    if (threadIdx.x == 0) {
        int s = 0;
        for (int c = 0; c < nch; c++) { g_coff[c] = s; s += g_ccnt[c]; }
        g_M = s;
    }
}

__global__ __launch_bounds__(1024) void k_candscatter(const float* __restrict__ betas, int n) {
    __shared__ int ws[32];
    int tid = threadIdx.x;
    int t = blockIdx.x * CHUNK + tid;
    int pred = (t < n) && (betas[t] >= MINBETA);
    int lr = blkscan_excl(pred, tid, ws);
    if (pred) {
        unsigned bits = __float_as_uint(betas[t]);
        uint64_t m = (~bits) & 0x7FFFFFu;           // exponent constant on [0.8,1)
        g_keyA[g_coff[blockIdx.x] + lr] = (m << IDXBITS) | (unsigned)t;
    }
}

__global__ __launch_bounds__(1024) void k_histR(int srcSel, int shift, int nb) {
    __shared__ int h[4096];
    int tid = threadIdx.x;
    for (int b = tid; b < nb; b += 1024) h[b] = 0;
    __syncthreads();
    const uint64_t* keys = srcSel ? g_keyB : g_keyA;
    int M = g_M;
    int t = blockIdx.x * CHUNK + tid;
    if (t < M) atomicAdd(&h[(int)((keys[t] >> shift) & (nb - 1))], 1);
    __syncthreads();
    for (int b = tid; b < nb; b += 1024) g_hist[blockIdx.x * NBPAD + b] = h[b];
}

__global__ void k_colsum(int nch, int nbFixed, int useC) {
    int nb = useC ? (g_nC + 1) : nbFixed;
    int b = blockIdx.x * blockDim.x + threadIdx.x;
    if (b < nb) {
        int s = 0;
        for (int c = 0; c < nch; c++) s += g_hist[c * NBPAD + b];
        g_total[b] = s;
    }
}

__global__ __launch_bounds__(1024) void k_scan(int nbFixed, int useC, float* psrs, int finalMode) {
    __shared__ int ws[32];
    int nb = useC ? (g_nC + 1) : nbFixed;
    int tid = threadIdx.x;
    const int IT = 9;
    int base = tid * IT;
    int loc[IT]; int s = 0;
    #pragma unroll
    for (int j = 0; j < IT; j++) {
        loc[j] = (base + j < nb) ? g_total[base + j] : 0;
        s += loc[j];
    }
    int ex = blkscan_excl(s, tid, ws);
    int run = ex;
    #pragma unroll
    for (int j = 0; j < IT; j++) {
        if (base + j < nb) g_start[base + j] = run;
        run += loc[j];
    }
    if (finalMode) {
        int occ[IT]; int so = 0;
        #pragma unroll
        for (int j = 0; j < IT; j++) { occ[j] = (base + j < nb && loc[j] > 0) ? 1 : 0; so += occ[j]; }
        int ex2 = blkscan_excl(so, tid, ws);
        int run2 = ex2, runS = ex;
        #pragma unroll
        for (int j = 0; j < IT; j++) {
            if (base + j < nb) {
                g_dense[base + j] = run2;
                if (occ[j]) psrs[run2] = (float)runS;
                run2 += occ[j];
            }
            runS += loc[j];
        }
        if (tid == 0) psrs[0] = 0.0f;
    }
}

__global__ void k_offsets(int nch, int nbFixed, int useC) {
    int nb = useC ? (g_nC + 1) : nbFixed;
    int b = blockIdx.x * blockDim.x + threadIdx.x;
    if (b >= nb) return;
    int run = g_start[b];
    for (int c = 0; c < nch; c++) {
        int idx = c * NBPAD + b;
        int t = g_hist[idx];
        g_hist[idx] = run;
        run += t;
    }
}

__global__ __launch_bounds__(1024) void k_scatterR(int srcSel, int shift, int nb) {
    __shared__ int dig[CHUNK];
    __shared__ uint64_t ky[CHUNK];
    const uint64_t* in = srcSel ? g_keyB : g_keyA;
    uint64_t* out = srcSel ? g_keyA : g_keyB;
    int tid = threadIdx.x;
    int M = g_M;
    int t = blockIdx.x * CHUNK + tid;
    int d = -7;
    if (t < M) {
        uint64_t k = in[t];
        ky[tid] = k;
        d = (int)((k >> shift) & (nb - 1));
    }
    dig[tid] = d;
    __syncthreads();
    int lr = 0;
    for (int q = 0; q < tid; q++) lr += (dig[q] == d);
    if (t < M) out[g_hist[blockIdx.x * NBPAD + d] + lr] = ky[tid];
}

// ---------------- greedy NMS with incremental smem spatial grid ----------------
// smem layout (bytes):
#define GS_SCP   0          // float4[MAXCG]      32768
#define GS_HEAD  32768      // int[GCELLS]        10648
#define GS_NXT   43416      // int[MAXCG]          8192
#define GS_CHX   51608      // float[1024]         4096
#define GS_CHY   55704
#define GS_CHZ   59800
#define GS_CHSEG 63896
#define GS_CHIDX 67992
#define GS_SALV  72088      // unsigned[32]         128
#define GREEDY_SMEM 72320

__global__ __launch_bounds__(1024) void k_greedy(const float* __restrict__ cc,
                                                 const int* __restrict__ rs, int ns) {
    extern __shared__ char sm[];
    float4*   scp   = (float4*)(sm + GS_SCP);
    int*      head  = (int*)   (sm + GS_HEAD);
    int*      nxt   = (int*)   (sm + GS_NXT);
    float*    chx   = (float*) (sm + GS_CHX);
    float*    chy   = (float*) (sm + GS_CHY);
    float*    chz   = (float*) (sm + GS_CHZ);
    int*      chseg = (int*)   (sm + GS_CHSEG);
    int*      chidx = (int*)   (sm + GS_CHIDX);
    unsigned* salv  = (unsigned*)(sm + GS_SALV);
    __shared__ int snC, sh_next;
    __shared__ int sbound[8];
    int tid = threadIdx.x;
    for (int c = tid; c < GCELLS; c += 1024) head[c] = -1;
    if (tid == 0) snC = 0;
    int nsb = ns - 2;
    if (tid < nsb) sbound[tid] = rs[tid + 1];
    __syncthreads();

    int M = g_M;
    int nchunks = (M + CHUNK - 1) / CHUNK;
    for (int ch = 0; ch < nchunks; ch++) {
        int t = ch * CHUNK + tid;
        bool valid = t < M;
        float x = 1e30f, y = 1e30f, z = 1e30f;
        int seg = -1, oi = 0;
        if (valid) {
            oi = (int)(g_keyA[t] & IDXMASK);
            x = cc[3 * oi]; y = cc[3 * oi + 1]; z = cc[3 * oi + 2];
            seg = 0;
            for (int j = 0; j < nsb; j++) seg += (oi >= sbound[j]);
        }
        chx[tid] = x; chy[tid] = y; chz[tid] = z; chseg[tid] = seg; chidx[tid] = oi;

        // filter: dead if any existing cpoint within radius (grid query)
        bool pending = valid;
        if (pending) {
            int cix = (int)floorf((x + GHALF) * CINV);
            int ciy = (int)floorf((y + GHALF) * CINV);
            int ciz = (int)floorf((z + GHALF) * CINV);
            int x0 = max(0, cix - 1), x1 = min(GD - 1, cix + 1);
            int y0 = max(0, ciy - 1), y1 = min(GD - 1, ciy + 1);
            int z0 = max(0, ciz - 1), z1 = min(GD - 1, ciz + 1);
            bool hit = false;
            for (int zz = z0; zz <= z1 && !hit; zz++)
                for (int yy = y0; yy <= y1 && !hit; yy++)
                    for (int xx = x0; xx <= x1 && !hit; xx++) {
                        int c = head[((seg * GD + zz) * GD + yy) * GD + xx];
                        while (c >= 0) {
                            float4 p = scp[c];
                            if (dist2(x, y, z, p.x, p.y, p.z) <= RAD2) { hit = true; break; }
                            c = nxt[c];
                        }
                    }
            pending = !hit;
        }
        unsigned bal = __ballot_sync(0xffffffffu, pending);
        if ((tid & 31) == 0) salv[tid >> 5] = bal;
        __syncthreads();

        // resolve: accept pending candidates in order; each accept kills in-radius later pendings
        while (true) {
            if (tid < 32) {
                unsigned w = salv[tid];
                int cand = w ? ((tid << 5) + __ffs(w) - 1) : CHUNK;
                #pragma unroll
                for (int o = 16; o; o >>= 1) cand = min(cand, __shfl_down_sync(0xffffffffu, cand, o));
                if (tid == 0) sh_next = cand;
            }
            __syncthreads();
            int j = sh_next;
            if (j >= CHUNK) break;
            float sx = chx[j], sy = chy[j], sz = chz[j];
            int sseg = chseg[j];
            if (tid == 0) {
                int c = snC;
                if (c < MAXCG) {
                    scp[c] = make_float4(sx, sy, sz, __int_as_float(chidx[j]));
                    int cell = cell_of(sx, sy, sz, sseg);
                    nxt[c] = head[cell]; head[cell] = c;
                    snC = c + 1;
                }
                atomicAnd(&salv[j >> 5], ~(1u << (j & 31)));
            }
            if (tid == j) pending = false;
            if (pending && tid > j && seg == sseg) {
                if (dist2(x, y, z, sx, sy, sz) <= RAD2) {
                    atomicAnd(&salv[tid >> 5], ~(1u << (tid & 31)));
                    pending = false;
                }
            }
            __syncthreads();
        }
    }
    __syncthreads();
    int nC = snC;
    for (int c = tid; c < nC; c += 1024) g_cp[c] = scp[c];
    for (int c = tid; c < nC; c += 1024) g_nxtG[c] = nxt[c];
    for (int c = tid; c < GCELLS; c += 1024) g_headG[c] = head[c];
    if (tid == 0) g_nC = nC;
}

// sort cpoint original indices ascending; greedy-rank -> (1-based) bin
#define SORTN 2048
__global__ __launch_bounds__(1024) void k_cpsort() {
    __shared__ uint64_t sk[SORTN];
    int nC = g_nC;
    int tid = threadIdx.x;
    for (int e = tid; e < SORTN; e += 1024)
        sk[e] = (e < nC)
            ? ((((uint64_t)(unsigned)__float_as_int(g_cp[e].w)) << 12) | (unsigned)e)
            : ~0ull;
    __syncthreads();
    for (int k = 2; k <= SORTN; k <<= 1)
        for (int j = k >> 1; j > 0; j >>= 1) {
            for (int e = tid; e < SORTN; e += 1024) {
                int x = e ^ j;
                if (x > e) {
                    uint64_t a = sk[e], b = sk[x];
                    bool up = ((e & k) == 0);
                    if ((a > b) == up) { sk[e] = b; sk[x] = a; }
                }
            }
            __syncthreads();
        }
    for (int r = tid; r < nC; r += 1024)
        g_cpid2bin[(int)(sk[r] & 0xFFFu)] = r + 1;
}

// assignment: min greedy rank cpoint within radius (grid query)
#define PH2_SMEM (32768 + 10648 + 8192 + 64)
__global__ __launch_bounds__(512) void k_phase2(const float* __restrict__ cc,
                                                const int* __restrict__ rs, int ns,
                                                int n, float* __restrict__ asso_out) {
    extern __shared__ char sm[];
    float4* scp  = (float4*)(sm);
    int*    head = (int*)(sm + 32768);
    int*    nxt  = (int*)(sm + 43416);
    __shared__ int sbound[8];
    __shared__ int s_nC;
    int tid = threadIdx.x;
    if (tid == 0) s_nC = g_nC;
    int nsb = ns - 2;
    if (tid < nsb) sbound[tid] = rs[tid + 1];
    __syncthreads();
    int nC = s_nC;
    for (int c = tid; c < nC; c += blockDim.x) { scp[c] = g_cp[c]; nxt[c] = g_nxtG[c]; }
    for (int c = tid; c < GCELLS; c += blockDim.x) head[c] = g_headG[c];
    __syncthreads();

    int i = blockIdx.x * blockDim.x + tid;
    if (i >= n) return;
    float x = cc[3 * i], y = cc[3 * i + 1], z = cc[3 * i + 2];
    int seg = 0;
    for (int j = 0; j < nsb; j++) seg += (i >= sbound[j]);
    int cix = (int)floorf((x + GHALF) * CINV);
    int ciy = (int)floorf((y + GHALF) * CINV);
    int ciz = (int)floorf((z + GHALF) * CINV);
    int x0 = max(0, cix - 1), x1 = min(GD - 1, cix + 1);
    int y0 = max(0, ciy - 1), y1 = min(GD - 1, ciy + 1);
    int z0 = max(0, ciz - 1), z1 = min(GD - 1, ciz + 1);
    int best = 0x7fffffff;
    for (int zz = z0; zz <= z1; zz++)
        for (int yy = y0; yy <= y1; yy++)
            for (int xx = x0; xx <= x1; xx++) {
                int c = head[((seg * GD + zz) * GD + yy) * GD + xx];
                while (c >= 0) {
                    float4 p = scp[c];
                    if (c < best && dist2(x, y, z, p.x, p.y, p.z) <= RAD2) best = c;
                    c = nxt[c];
                }
            }
    int g = (best == 0x7fffffff) ? -1 : best;
    g_g[i] = g;
    asso_out[i] = (float)((g < 0) ? -1 : __float_as_int(scp[best].w));
}

__global__ __launch_bounds__(1024) void k_hist2(int n) {
    __shared__ int h[NBPAD];
    int nb = g_nC + 1;
    int tid = threadIdx.x;
    for (int b = tid; b < nb; b += 1024) h[b] = 0;
    __syncthreads();
    int t = blockIdx.x * CHUNK + tid;
    if (t < n) {
        int g = g_g[t];
        int b = (g < 0) ? 0 : g_cpid2bin[g];
        atomicAdd(&h[b], 1);
    }
    __syncthreads();
    for (int b = tid; b < nb; b += 1024) g_hist[blockIdx.x * NBPAD + b] = h[b];
}

__global__ __launch_bounds__(1024) void k_scatter2(int n, float* __restrict__ sids,
                                                   float* __restrict__ belongs) {
    __shared__ int dig[CHUNK];
    int tid = threadIdx.x;
    int t = blockIdx.x * CHUNK + tid;
    int d = -7;
    if (t < n) {
        int g = g_g[t];
        d = (g < 0) ? 0 : g_cpid2bin[g];
    }
    dig[tid] = d;
    __syncthreads();
    int lr = 0;
    for (int q = 0; q < tid; q++) lr += (dig[q] == d);
    if (t < n) {
        int pos = g_hist[blockIdx.x * NBPAD + d] + lr;
        g_pos[t] = pos;
        sids[pos] = (float)t;
        belongs[pos] = (float)g_dense[d];
    }
}

__global__ __launch_bounds__(512) void k_copy(const float* __restrict__ data,
                                              float* __restrict__ sdata, int n, int F) {
    int warp = (blockIdx.x * blockDim.x + threadIdx.x) >> 5;
    int lane = threadIdx.x & 31;
    if (warp >= n) return;
    int pos = g_pos[warp];
    const float4* src = (const float4*)(data + (size_t)warp * F);
    float4* dst = (float4*)(sdata + (size_t)pos * F);
    int nf4 = F >> 2;
    for (int k = lane; k < nf4; k += 32) dst[k] = src[k];
}

// ---------------- host launcher ----------------
extern "C" void kernel_launch(void* const* d_in, const int* in_sizes, int n_in,
                              void* d_out, int out_size) {
    const float* data  = (const float*)d_in[0];
    const float* cc    = (const float*)d_in[1];
    const float* betas = (const float*)d_in[2];
    const int*   rs    = (const int*)d_in[3];
    int N = in_sizes[2];
    int F = in_sizes[0] / N;
    int ns = in_sizes[3];

    float* out    = (float*)d_out;
    float* sdata  = out;
    float* psrs   = out + (size_t)N * F;
    float* sids   = psrs + (N + 1);
    float* asso   = sids + N;
    float* belongs= asso + N;

    int nch = (N + CHUNK - 1) / CHUNK;

    cudaFuncSetAttribute(k_greedy, cudaFuncAttributeMaxDynamicSharedMemorySize, GREEDY_SMEM);
    cudaFuncSetAttribute(k_phase2, cudaFuncAttributeMaxDynamicSharedMemorySize, PH2_SMEM);

    // candidate compaction (index-stable); also inits psrs padding
    k_candcount<<<nch, 1024>>>(betas, N, psrs);
    k_candscan<<<1, 32>>>(nch);
    k_candscatter<<<nch, 1024>>>(betas, N);

    // 2-pass LSD radix on mantissa bits (stable -> idx tiebreak)
    k_histR<<<nch, 1024>>>(0, 21, 4096);
    k_colsum<<<(NBPAD + 255) / 256, 256>>>(nch, 4096, 0);
    k_scan<<<1, 1024>>>(4096, 0, psrs, 0);
    k_offsets<<<(NBPAD + 255) / 256, 256>>>(nch, 4096, 0);
    k_scatterR<<<nch, 1024>>>(0, 21, 4096);
    k_histR<<<nch, 1024>>>(1, 33, 2048);
    k_colsum<<<(NBPAD + 255) / 256, 256>>>(nch, 2048, 0);
    k_scan<<<1, 1024>>>(2048, 0, psrs, 0);
    k_offsets<<<(NBPAD + 255) / 256, 256>>>(nch, 2048, 0);
    k_scatterR<<<nch, 1024>>>(1, 33, 2048);

    // greedy NMS with smem spatial grid
    k_greedy<<<1, 1024, GREEDY_SMEM>>>(cc, rs, ns);
    k_cpsort<<<1, 1024>>>();
    // per-point assignment via grid (min greedy rank within radius)
    k_phase2<<<(N + 511) / 512, 512, PH2_SMEM>>>(cc, rs, ns, N, asso);

    // final stable counting sort by bin
    k_hist2<<<nch, 1024>>>(N);
    k_colsum<<<(NBPAD + 255) / 256, 256>>>(nch, 0, 1);
    k_scan<<<1, 1024>>>(0, 1, psrs, 1);
    k_offsets<<<(NBPAD + 255) / 256, 256>>>(nch, 0, 1);
    k_scatter2<<<nch, 1024>>>(N, sids, belongs);

    // permute data rows (HBM-bound: ~205 MB)
    k_copy<<<(N + 15) / 16, 512>>>(data, sdata, N, F);
}

// round 4
// speedup vs baseline: 1.4466x; 1.0236x over previous
#include <cuda_runtime.h>
#include <cstdint>

// ---------------- constants ----------------
#define CHUNK   1024
#define MAXN    262144
#define MAXCH   256
#define NBPAD   4352
#define IDXBITS 21
#define IDXMASK ((1u<<IDXBITS)-1u)
#define RAD2    2.25f
#define MINBETA 0.8f

#define GD      11
#define GHALF   8.25f
#define CINV    0.666f
#define GCELLS  (2*GD*GD*GD)    // 2662
#define MAXCG   2048

// ---------------- device scratch ----------------
static __device__ uint64_t g_keyA[MAXN];
static __device__ uint64_t g_keyB[MAXN];
static __device__ int      g_hist [MAXCH * NBPAD];
static __device__ int      g_hist2[MAXCH * NBPAD];
static __device__ int      g_dense[NBPAD];
static __device__ int      g_ccnt[MAXCH];
static __device__ int      g_coff[MAXCH];
static __device__ int      g_done;
static __device__ float4   g_cp[MAXCG];
static __device__ int      g_headG[GCELLS];
static __device__ int      g_nxtG[MAXCG];
static __device__ int      g_cpid2bin[MAXCG];
static __device__ int      g_g[MAXN];          // final bin per point
static __device__ int      g_pos[MAXN];
static __device__ int      g_M;
static __device__ int      g_nC;

// ---------------- helpers ----------------
__device__ __forceinline__ int blkscan_excl(int v, int tid, int* ws) {
    __syncthreads();
    int lane = tid & 31, w = tid >> 5;
    int inc = v;
    #pragma unroll
    for (int o = 1; o < 32; o <<= 1) {
        int u = __shfl_up_sync(0xffffffffu, inc, o);
        if (lane >= o) inc += u;
    }
    if (lane == 31) ws[w] = inc;
    __syncthreads();
    if (tid < 32) {
        int s = ws[tid];
        #pragma unroll
        for (int o = 1; o < 32; o <<= 1) {
            int u = __shfl_up_sync(0xffffffffu, s, o);
            if (lane >= o) s += u;
        }
        ws[tid] = s;
    }
    __syncthreads();
    return (w ? ws[w - 1] : 0) + inc - v;
}

__device__ __forceinline__ float dist2(float ax, float ay, float az,
                                       float bx, float by, float bz) {
    float dx = ax - bx, dy = ay - by, dz = az - bz;
    return fmaf(dz, dz, fmaf(dy, dy, dx * dx));   // matches XLA fma chain
}

__device__ __forceinline__ int cell1(float v) {
    int c = (int)floorf((v + GHALF) * CINV);
    return c < 0 ? 0 : (c > GD - 1 ? GD - 1 : c);
}
__device__ __forceinline__ int cell_of(float x, float y, float z, int seg) {
    return ((seg * GD + cell1(z)) * GD + cell1(y)) * GD + cell1(x);
}

// warp-sequential stable rank: rank of element among equal digits in block (tid order)
__device__ __forceinline__ int stable_rank(int d, bool valid, int tid, int* cnt) {
    int lane = tid & 31, w = tid >> 5;
    unsigned vm = __ballot_sync(0xffffffffu, valid);
    int rank = 0;
    for (int ww = 0; ww < 32; ++ww) {
        if (w == ww && valid) {
            unsigned mm = __match_any_sync(vm, d);
            int ldr = __ffs(mm) - 1;
            int lower = __popc(mm & ((1u << lane) - 1u));
            int base = 0;
            if (lane == ldr) base = atomicAdd(&cnt[d], __popc(mm));
            base = __shfl_sync(mm, base, ldr);
            rank = base + lower;
        }
        __syncthreads();
    }
    return rank;
}

// ---------------- kernels ----------------
// 1. count candidates per chunk, zero hist buffers, init psrs; last block scans
__global__ __launch_bounds__(1024) void k_candcount(const float* __restrict__ betas, int n,
                                                    float* __restrict__ psrs) {
    int gsz = gridDim.x;
    int tot = MAXCH * NBPAD;
    for (int idx = blockIdx.x * 1024 + threadIdx.x; idx < tot; idx += gsz * 1024) {
        g_hist[idx] = 0; g_hist2[idx] = 0;
    }
    int t = blockIdx.x * 1024 + threadIdx.x;
    if (t <= n) psrs[t] = (float)n;
    int pred = (t < n) && (betas[t] >= MINBETA);
    int cnt = __syncthreads_count(pred);
    if (threadIdx.x == 0) {
        g_ccnt[blockIdx.x] = cnt;
        __threadfence();
        if (atomicAdd(&g_done, 1) == gsz - 1) {
            int s = 0;
            for (int c = 0; c < gsz; c++) { g_coff[c] = s; s += g_ccnt[c]; }
            g_M = s;
            g_done = 0;
        }
    }
}

// 2. compact candidate keys + fused pass-1 histogram
__global__ __launch_bounds__(1024) void k_candscatter(const float* __restrict__ betas, int n) {
    __shared__ int ws[32];
    int tid = threadIdx.x;
    int t = blockIdx.x * 1024 + tid;
    int pred = (t < n) && (betas[t] >= MINBETA);
    int lr = blkscan_excl(pred, tid, ws);
    if (pred) {
        unsigned bits = __float_as_uint(betas[t]);
        uint64_t m = (~bits) & 0x7FFFFFu;
        uint64_t key = (m << IDXBITS) | (unsigned)t;
        int dest = g_coff[blockIdx.x] + lr;
        g_keyA[dest] = key;
        int d = (int)((key >> 21) & 4095u);
        atomicAdd(&g_hist[(dest >> 10) * NBPAD + d], 1);
    }
}

// 3. single-block fused colsum + scan + in-place offsets (+ final psrs/dense)
__global__ __launch_bounds__(1024) void k_prefix(int useH2, int nbFixed, int nchFix,
                                                 int modeM, int finalMode,
                                                 float* __restrict__ psrs) {
    __shared__ int ws[32];
    __shared__ int stot[4096];
    int* hist = useH2 ? g_hist2 : g_hist;
    int nb = finalMode ? (g_nC + 1) : nbFixed;
    int nch = modeM ? ((g_M + 1023) >> 10) : nchFix;
    int tid = threadIdx.x;
    int carry = 0;
    #pragma unroll
    for (int j = 0; j < 4; j++) {
        int b = j * 1024 + tid;
        int v = 0;
        if (b < nb)
            for (int c = 0; c < nch; c++) v += hist[c * NBPAD + b];
        stot[b] = v;
        int ex = blkscan_excl(v, tid, ws);
        int run = carry + ex;
        if (b < nb) {
            for (int c = 0; c < nch; c++) {
                int tmp = hist[c * NBPAD + b];
                hist[c * NBPAD + b] = run;
                run += tmp;
            }
        }
        carry += ws[31];
    }
    if (finalMode) {
        int carry2 = 0;
        #pragma unroll
        for (int j = 0; j < 4; j++) {
            int b = j * 1024 + tid;
            int v = (b < nb) ? stot[b] : 0;
            int occ = (b < nb && v > 0) ? 1 : 0;
            int exo = blkscan_excl(occ, tid, ws);
            int dr = carry2 + exo;
            if (b < nb) {
                g_dense[b] = dr;
                if (occ) psrs[dr] = (float)hist[b];   // hist[chunk0][b] == start[b]
            }
            carry2 += ws[31];
        }
        if (tid == 0) psrs[0] = 0.0f;
    }
}

// 4/6. stable radix scatter with match ranks; optional fused next-pass histogram
__global__ __launch_bounds__(1024) void k_scatterR(int srcSel, int shift, int nb,
                                                   int useH2, int fuse) {
    int M = g_M;
    if ((blockIdx.x << 10) >= M) return;
    __shared__ int cnt[4096];
    const uint64_t* in = srcSel ? g_keyB : g_keyA;
    uint64_t* out = srcSel ? g_keyA : g_keyB;
    int* hist = useH2 ? g_hist2 : g_hist;
    int tid = threadIdx.x;
    for (int b = tid; b < nb; b += 1024) cnt[b] = 0;
    int t = blockIdx.x * 1024 + tid;
    bool valid = t < M;
    uint64_t k = 0; int d = 0;
    if (valid) { k = in[t]; d = (int)((k >> shift) & (uint64_t)(nb - 1)); }
    __syncthreads();
    int rank = stable_rank(d, valid, tid, cnt);
    if (valid) {
        int pos = hist[blockIdx.x * NBPAD + d] + rank;
        out[pos] = k;
        if (fuse) {
            int d2 = (int)((k >> 33) & 2047u);
            atomicAdd(&g_hist2[(pos >> 10) * NBPAD + d2], 1);
        }
    }
}

// 7. greedy NMS (single block) + cpoint rank map in tail
#define GS_SCP   0
#define GS_NXT   32768
#define GS_HEAD  40960
#define GS_CHX   51616
#define GS_CHY   55712
#define GS_CHZ   59808
#define GS_CHSEG 63904
#define GS_CHIDX 68000
#define GS_SALV  72096
#define GREEDY_SMEM 72320

__global__ __launch_bounds__(1024) void k_greedy(const float* __restrict__ cc,
                                                 const int* __restrict__ rs, int ns) {
    extern __shared__ char sm[];
    float4*   scp   = (float4*)(sm + GS_SCP);
    int*      nxt   = (int*)   (sm + GS_NXT);
    int*      head  = (int*)   (sm + GS_HEAD);
    float*    chx   = (float*) (sm + GS_CHX);
    float*    chy   = (float*) (sm + GS_CHY);
    float*    chz   = (float*) (sm + GS_CHZ);
    int*      chseg = (int*)   (sm + GS_CHSEG);
    int*      chidx = (int*)   (sm + GS_CHIDX);
    unsigned* salv  = (unsigned*)(sm + GS_SALV);
    __shared__ int snC;
    __shared__ int sbound[8];
    int tid = threadIdx.x;
    int lane = tid & 31, w = tid >> 5;
    for (int c = tid; c < GCELLS; c += 1024) head[c] = -1;
    if (tid == 0) snC = 0;
    int nsb = ns - 2;
    if (tid < nsb) sbound[tid] = rs[tid + 1];
    __syncthreads();

    int M = g_M;
    int nchunks = (M + CHUNK - 1) / CHUNK;
    for (int ch = 0; ch < nchunks; ch++) {
        int t = ch * CHUNK + tid;
        bool valid = t < M;
        float x = 1e30f, y = 1e30f, z = 1e30f;
        int seg = -1, oi = 0;
        if (valid) {
            oi = (int)(g_keyA[t] & IDXMASK);
            x = cc[3 * oi]; y = cc[3 * oi + 1]; z = cc[3 * oi + 2];
            seg = 0;
            for (int j = 0; j < nsb; j++) seg += (oi >= sbound[j]);
        }
        chx[tid] = x; chy[tid] = y; chz[tid] = z; chseg[tid] = seg; chidx[tid] = oi;

        // filter against existing cpoints (27-cell walk, unrolled: independent head loads)
        bool hit = false;
        if (valid) {
            int cix = (int)floorf((x + GHALF) * CINV);
            int ciy = (int)floorf((y + GHALF) * CINV);
            int ciz = (int)floorf((z + GHALF) * CINV);
            #pragma unroll
            for (int dz = -1; dz <= 1; dz++) {
                int zz = min(GD - 1, max(0, ciz + dz));
                #pragma unroll
                for (int dy = -1; dy <= 1; dy++) {
                    int yy = min(GD - 1, max(0, ciy + dy));
                    #pragma unroll
                    for (int dx = -1; dx <= 1; dx++) {
                        int xx = min(GD - 1, max(0, cix + dx));
                        int c = head[((seg * GD + zz) * GD + yy) * GD + xx];
                        while (c >= 0 && !hit) {
                            float4 p = scp[c];
                            if (dist2(x, y, z, p.x, p.y, p.z) <= RAD2) hit = true;
                            c = nxt[c];
                        }
                    }
                }
            }
        }
        bool pending = valid && !hit;
        unsigned bal = __ballot_sync(0xffffffffu, pending);
        if (lane == 0) salv[w] = bal;
        __syncthreads();

        // warp-0 resolves: accept pendings in index order, kill in-radius later pendings
        if (w == 0) {
            unsigned wL = salv[lane];
            int nC = snC;
            while (true) {
                int cand = wL ? (lane * 32 + __ffs(wL) - 1) : 2048;
                #pragma unroll
                for (int o = 16; o; o >>= 1)
                    cand = min(cand, __shfl_xor_sync(0xffffffffu, cand, o));
                if (cand >= 2048) break;
                int j = cand;
                if (lane == (j >> 5)) wL &= ~(1u << (j & 31));
                float sx = chx[j], sy = chy[j], sz = chz[j];
                int sseg = chseg[j];
                if (nC < MAXCG) {
                    if (lane == 0) {
                        scp[nC] = make_float4(sx, sy, sz, __int_as_float(chidx[j]));
                        int cell = cell_of(sx, sy, sz, sseg);
                        nxt[nC] = head[cell]; head[cell] = nC;
                    }
                    nC++;
                }
                unsigned rem = wL;
                while (rem) {
                    int b = __ffs(rem) - 1; rem &= rem - 1;
                    int jj = lane * 32 + b;
                    if (chseg[jj] == sseg &&
                        dist2(chx[jj], chy[jj], chz[jj], sx, sy, sz) <= RAD2)
                        wL &= ~(1u << b);
                }
            }
            if (lane == 0) snC = nC;
        }
        __syncthreads();
    }

    int nC = snC;
    for (int e = tid; e < nC; e += 1024) {
        float4 p = scp[e];
        g_cp[e] = p;
        g_nxtG[e] = nxt[e];
        int myidx = __float_as_int(p.w);
        int cnt = 1;
        for (int e2 = 0; e2 < nC; e2++)
            cnt += (__float_as_int(scp[e2].w) < myidx);
        g_cpid2bin[e] = cnt;          // 1-based bin (bin 0 = unassigned)
    }
    for (int c = tid; c < GCELLS; c += 1024) g_headG[c] = head[c];
    if (tid == 0) g_nC = nC;
}

// 8. per-point assignment (min greedy rank within radius) + fused final histogram
#define P2_SCP  0
#define P2_NXT  32768
#define P2_HEAD 40960
#define P2_C2B  51616
#define P2_HIST 59808
#define P2_SMEM 68032
#define P2_NBMAX 2052

__global__ __launch_bounds__(1024) void k_phase2(const float* __restrict__ cc,
                                                 const int* __restrict__ rs, int ns,
                                                 int n, float* __restrict__ asso_out) {
    extern __shared__ char sm[];
    float4* scp  = (float4*)(sm + P2_SCP);
    int*    nxt  = (int*)(sm + P2_NXT);
    int*    head = (int*)(sm + P2_HEAD);
    int*    c2b  = (int*)(sm + P2_C2B);
    int*    hist = (int*)(sm + P2_HIST);
    __shared__ int sbound[8];
    __shared__ int s_nC;
    int tid = threadIdx.x;
    if (tid == 0) s_nC = g_nC;
    int nsb = ns - 2;
    if (tid < nsb) sbound[tid] = rs[tid + 1];
    __syncthreads();
    int nC = s_nC;
    int nb = nC + 1;
    for (int c = tid; c < nC; c += 1024) {
        scp[c] = g_cp[c]; nxt[c] = g_nxtG[c]; c2b[c] = g_cpid2bin[c];
    }
    for (int c = tid; c < GCELLS; c += 1024) head[c] = g_headG[c];
    for (int b = tid; b < nb; b += 1024) hist[b] = 0;
    __syncthreads();

    int i = blockIdx.x * 1024 + tid;
    if (i < n) {
        float x = cc[3 * i], y = cc[3 * i + 1], z = cc[3 * i + 2];
        int seg = 0;
        for (int j = 0; j < nsb; j++) seg += (i >= sbound[j]);
        int cix = (int)floorf((x + GHALF) * CINV);
        int ciy = (int)floorf((y + GHALF) * CINV);
        int ciz = (int)floorf((z + GHALF) * CINV);
        int best = 0x7fffffff;
        #pragma unroll
        for (int dz = -1; dz <= 1; dz++) {
            int zz = min(GD - 1, max(0, ciz + dz));
            #pragma unroll
            for (int dy = -1; dy <= 1; dy++) {
                int yy = min(GD - 1, max(0, ciy + dy));
                #pragma unroll
                for (int dx = -1; dx <= 1; dx++) {
                    int xx = min(GD - 1, max(0, cix + dx));
                    int c = head[((seg * GD + zz) * GD + yy) * GD + xx];
                    while (c >= 0) {
                        float4 p = scp[c];
                        if (c < best && dist2(x, y, z, p.x, p.y, p.z) <= RAD2) best = c;
                        c = nxt[c];
                    }
                }
            }
        }
        int bin, assov;
        if (best == 0x7fffffff) { bin = 0; assov = -1; }
        else { bin = c2b[best]; assov = __float_as_int(scp[best].w); }
        asso_out[i] = (float)assov;
        g_g[i] = bin;
        atomicAdd(&hist[bin], 1);
    }
    __syncthreads();
    for (int b = tid; b < nb; b += 1024) g_hist[blockIdx.x * NBPAD + b] = hist[b];
}

// 10. final stable scatter
__global__ __launch_bounds__(1024) void k_scatterF(int n, float* __restrict__ sids,
                                                   float* __restrict__ belongs) {
    __shared__ int cnt[4096];
    int nb = g_nC + 1;
    int tid = threadIdx.x;
    for (int b = tid; b < nb; b += 1024) cnt[b] = 0;
    int t = blockIdx.x * 1024 + tid;
    bool valid = t < n;
    int d = valid ? g_g[t] : 0;
    __syncthreads();
    int rank = stable_rank(d, valid, tid, cnt);
    if (valid) {
        int pos = g_hist[blockIdx.x * NBPAD + d] + rank;
        g_pos[t] = pos;
        sids[pos] = (float)t;
        belongs[pos] = (float)g_dense[d];
    }
}

// 11. permute data rows
__global__ __launch_bounds__(512) void k_copy(const float* __restrict__ data,
                                              float* __restrict__ sdata, int n, int F) {
    int warp = (blockIdx.x * blockDim.x + threadIdx.x) >> 5;
    int lane = threadIdx.x & 31;
    if (warp >= n) return;
    int pos = g_pos[warp];
    const float4* src = (const float4*)(data + (size_t)warp * F);
    float4* dst = (float4*)(sdata + (size_t)pos * F);
    int nf4 = F >> 2;
    for (int k = lane; k < nf4; k += 32) dst[k] = src[k];
}

// ---------------- host launcher ----------------
extern "C" void kernel_launch(void* const* d_in, const int* in_sizes, int n_in,
                              void* d_out, int out_size) {
    const float* data  = (const float*)d_in[0];
    const float* cc    = (const float*)d_in[1];
    const float* betas = (const float*)d_in[2];
    const int*   rs    = (const int*)d_in[3];
    int N = in_sizes[2];
    int F = in_sizes[0] / N;
    int ns = in_sizes[3];

    float* out     = (float*)d_out;
    float* sdata   = out;
    float* psrs    = out + (size_t)N * F;
    float* sids    = psrs + (N + 1);
    float* asso    = sids + N;
    float* belongs = asso + N;

    int nch = (N + CHUNK - 1) / CHUNK;

    cudaFuncSetAttribute(k_greedy, cudaFuncAttributeMaxDynamicSharedMemorySize, GREEDY_SMEM);
    cudaFuncSetAttribute(k_phase2, cudaFuncAttributeMaxDynamicSharedMemorySize, P2_SMEM);

    k_candcount<<<nch, 1024>>>(betas, N, psrs);
    k_candscatter<<<nch, 1024>>>(betas, N);
    k_prefix<<<1, 1024>>>(0, 4096, 0, 1, 0, psrs);            // pass1 offsets
    k_scatterR<<<nch, 1024>>>(0, 21, 4096, 0, 1);             // A->B, fuse hist2
    k_prefix<<<1, 1024>>>(1, 2048, 0, 1, 0, psrs);            // pass2 offsets
    k_scatterR<<<nch, 1024>>>(1, 33, 2048, 1, 0);             // B->A
    k_greedy<<<1, 1024, GREEDY_SMEM>>>(cc, rs, ns);
    k_phase2<<<nch, 1024, P2_SMEM>>>(cc, rs, ns, N, asso);    // + final hist
    k_prefix<<<1, 1024>>>(0, 0, nch, 0, 1, psrs);             // final offsets + psrs/dense
    k_scatterF<<<nch, 1024>>>(N, sids, belongs);
    k_copy<<<(N + 15) / 16, 512>>>(data, sdata, N, F);
}